// round 15
// baseline (speedup 1.0000x reference)
#include <cuda_runtime.h>
#include <cuda_bf16.h>
#include <math.h>
#include <stdint.h>

#define B_ 4
#define T_ 4096
#define D_ 1024
#define H_ 16
#define C_ 64
#define N_ 64
#define BT_ (B_*T_)
#define BHN_ (B_*H_*N_)

typedef unsigned long long u64;
struct alignas(16) u64x2 { u64 a, b; };

// ---------- scratch ----------
__device__ float g_v[BT_*D_];
__device__ float g_gate[BT_*H_];
__device__ float g_beta[BT_*H_];
__device__ float g_dec[BT_*H_];
__device__ __nv_bfloat16 g_rkd[BHN_*4096];
__device__ __nv_bfloat16 g_wkcd[BHN_*4096];   // NEGATED
__device__ __nv_bfloat16 g_vc[BHN_*4096];
__device__ __nv_bfloat16 g_wkdw[BHN_*4096];   // TRANSPOSED [d][token]
__device__ __nv_bfloat16 g_intra[BHN_*4096];
__device__ float g_elast[BHN_];
__device__ __nv_bfloat16 g_xb[BT_*D_];
__device__ __nv_bfloat16 g_ogb[BT_*D_];
__device__ __nv_bfloat16 g_wb0[D_*D_];
__device__ __nv_bfloat16 g_wb1[D_*D_];

__device__ __forceinline__ uint32_t smem_u32(const void* p){
    uint32_t a;
    asm("{ .reg .u64 t; cvta.to.shared.u64 t, %1; cvt.u32.u64 %0, t; }" : "=r"(a) : "l"(p));
    return a;
}
__device__ __forceinline__ u64 pk2(float x){
    u64 r; asm("mov.b64 %0, {%1,%1};" : "=l"(r) : "f"(x)); return r;
}
__device__ __forceinline__ u64 pkf2(float x, float y){
    u64 r; asm("mov.b64 %0, {%1,%2};" : "=l"(r) : "f"(x), "f"(y)); return r;
}
__device__ __forceinline__ void fma2(u64& d, u64 a, u64 b){
    asm("fma.rn.f32x2 %0, %1, %2, %0;" : "+l"(d) : "l"(a), "l"(b));
}
__device__ __forceinline__ float2 up2(u64 v){
    float2 f; asm("mov.b64 {%0,%1}, %2;" : "=f"(f.x), "=f"(f.y) : "l"(v)); return f;
}
__device__ __forceinline__ void cpa16(uint32_t d, const void* s){
    asm volatile("cp.async.cg.shared.global [%0], [%1], 16;" :: "r"(d), "l"(s));
}
__device__ __forceinline__ void cpa4(uint32_t d, const void* s){
    asm volatile("cp.async.ca.shared.global [%0], [%1], 4;" :: "r"(d), "l"(s));
}
__device__ __forceinline__ float4 ld4bf(const __nv_bfloat16* p){
    u64 raw = *(const u64*)p;
    unsigned lo = (unsigned)raw, hi = (unsigned)(raw>>32);
    float2 a = __bfloat1622float2(*(__nv_bfloat162*)&lo);
    float2 c = __bfloat1622float2(*(__nv_bfloat162*)&hi);
    return make_float4(a.x, a.y, c.x, c.y);
}

// ---------------- fp32 -> bf16 convert ----------------
__global__ __launch_bounds__(256) void cvt_kernel(const float* __restrict__ in,
                                                  __nv_bfloat16* __restrict__ out, int n4)
{
    int i = blockIdx.x*256 + threadIdx.x;
    if (i < n4){
        float4 v = ((const float4*)in)[i];
        __nv_bfloat162 a = __floats2bfloat162_rn(v.x, v.y);
        __nv_bfloat162 b = __floats2bfloat162_rn(v.z, v.w);
        ((__nv_bfloat162*)out)[2*i]   = a;
        ((__nv_bfloat162*)out)[2*i+1] = b;
    }
}

// ================= projections =================
#define XS_STRIDE 132
#define PROJ_SMEM ((128*XS_STRIDE + 128*48)*4)
__global__ __launch_bounds__(256) void proj_kernel(
    const float* __restrict__ x, const float* __restrict__ wg,
    const float* __restrict__ wb, const float* __restrict__ wa,
    const float* __restrict__ dtb, const float* __restrict__ alog)
{
    extern __shared__ float psm[];
    float* Xs = psm;
    float* Ws = psm + 128*XS_STRIDE;
    int t = threadIdx.x;
    int row = t & 127, og = t >> 7;
    int o0 = og*24;
    int r0 = blockIdx.x * 128;

    float acc[24];
    #pragma unroll
    for (int j=0;j<24;j++) acc[j]=0.f;

    for (int k0=0; k0<1024; k0+=128){
        #pragma unroll
        for (int i=0;i<16;i++){
            int f4 = i*256 + t;
            int m = f4 >> 5, kv = (f4 & 31)*4;
            float4 v = *(const float4*)&x[(size_t)(r0+m)*1024 + k0 + kv];
            *(float4*)&Xs[m*XS_STRIDE + kv] = v;
        }
        for (int e = t; e < 128*48; e += 256){
            int kk = e / 48, o = e % 48;
            const float* W = (o<16) ? wg : ((o<32) ? wb : wa);
            Ws[kk*48 + o] = W[(size_t)(k0+kk)*16 + (o & 15)];
        }
        __syncthreads();
        #pragma unroll 4
        for (int kk=0; kk<128; kk++){
            float xv = Xs[row*XS_STRIDE + kk];
            const float* wrow = &Ws[kk*48 + o0];
            #pragma unroll
            for (int j=0;j<24;j+=4){
                float4 w4 = *(const float4*)&wrow[j];
                acc[j]   += xv*w4.x; acc[j+1] += xv*w4.y;
                acc[j+2] += xv*w4.z; acc[j+3] += xv*w4.w;
            }
        }
        __syncthreads();
    }
    int rg = r0 + row;
    #pragma unroll
    for (int j=0;j<24;j++){
        int o = o0 + j;
        int h = o & 15, kind = o >> 4;
        float s = acc[j];
        if (kind==0)      g_gate[rg*16+h] = 1.f/(1.f+__expf(-s));
        else if (kind==1) g_beta[rg*16+h] = 1.f/(1.f+__expf(-s));
        else {
            float v = s + dtb[h];
            float sp = fmaxf(v,0.f) + log1pf(__expf(-fabsf(v)));
            g_dec[rg*16+h] = -__expf(alog[h])*sp;
        }
    }
}

// ================= bf16 mma GEMM, cp.async 3-stage =================
#define GS_A_STRIDE 20
#define GS_B_STRIDE 68
#define GS_A_TILE  (128*GS_A_STRIDE)
#define GS_B_TILE  (32*GS_B_STRIDE)
#define GS_STAGE   (GS_A_TILE + GS_B_TILE)
#define G_SMEM     (3*GS_STAGE*4)

__device__ __forceinline__ void ldsm4(unsigned r[4], uint32_t a){
    asm volatile("ldmatrix.sync.aligned.m8n8.x4.shared.b16 {%0,%1,%2,%3}, [%4];"
        : "=r"(r[0]),"=r"(r[1]),"=r"(r[2]),"=r"(r[3]) : "r"(a));
}
__device__ __forceinline__ void ldsm4t(unsigned r[4], uint32_t a){
    asm volatile("ldmatrix.sync.aligned.m8n8.x4.trans.shared.b16 {%0,%1,%2,%3}, [%4];"
        : "=r"(r[0]),"=r"(r[1]),"=r"(r[2]),"=r"(r[3]) : "r"(a));
}
__device__ __forceinline__ void mma_bf16(float* c, const unsigned* a, unsigned b0, unsigned b1){
    asm volatile("mma.sync.aligned.m16n8k16.row.col.f32.bf16.bf16.f32 "
      "{%0,%1,%2,%3}, {%4,%5,%6,%7}, {%8,%9}, {%0,%1,%2,%3};"
      : "+f"(c[0]),"+f"(c[1]),"+f"(c[2]),"+f"(c[3])
      : "r"(a[0]),"r"(a[1]),"r"(a[2]),"r"(a[3]),"r"(b0),"r"(b1));
}

__global__ __launch_bounds__(256) void hgemm(
    const __nv_bfloat16* __restrict__ A, const __nv_bfloat16* __restrict__ Bw,
    const float* __restrict__ R, float* __restrict__ C, int mode)
{
    extern __shared__ float gsm[];
    uint32_t sbase = smem_u32(gsm);

    int t = threadIdx.x, lane = t & 31, warp = t >> 5;
    int wm = warp >> 1, wn = warp & 1;
    int bm = blockIdx.y, bn = blockIdx.x;
    const __nv_bfloat16* Ab = A + (size_t)(bm*128)*1024;
    const __nv_bfloat16* Bb = Bw + (size_t)bn*128;

    float acc[2][8][4];
    #pragma unroll
    for (int mt=0;mt<2;mt++)
        #pragma unroll
        for (int j=0;j<8;j++)
            #pragma unroll
            for (int r=0;r<4;r++) acc[mt][j][r]=0.f;

    auto issue = [&](int it){
        uint32_t st = sbase + (uint32_t)(it % 3)*(GS_STAGE*4);
        #pragma unroll
        for (int u=0;u<2;u++){
            int row = u*64 + (t>>2), ch = t&3;
            uint32_t so = st + (uint32_t)((row*GS_A_STRIDE + ch*4)*4);
            cpa16(so, Ab + (size_t)row*1024 + it*32 + ch*8);
        }
        uint32_t sb = st + GS_A_TILE*4;
        #pragma unroll
        for (int u=0;u<2;u++){
            int row = u*16 + (t>>4), ch = t&15;
            uint32_t so = sb + (uint32_t)((row*GS_B_STRIDE + ch*4)*4);
            cpa16(so, Bb + (size_t)(it*32 + row)*1024 + ch*8);
        }
    };

    issue(0); asm volatile("cp.async.commit_group;" ::: "memory");
    issue(1); asm volatile("cp.async.commit_group;" ::: "memory");

    for (int it=0; it<32; it++){
        if (it < 31) asm volatile("cp.async.wait_group 1;" ::: "memory");
        else         asm volatile("cp.async.wait_group 0;" ::: "memory");
        __syncthreads();
        if (it+2 < 32){
            issue(it+2);
            asm volatile("cp.async.commit_group;" ::: "memory");
        }
        uint32_t sa = sbase + (uint32_t)(it % 3)*(GS_STAGE*4);
        uint32_t sb = sa + GS_A_TILE*4;
        #pragma unroll
        for (int s=0;s<2;s++){
            unsigned af[2][4], bfr[4][4];
            #pragma unroll
            for (int mt=0;mt<2;mt++){
                uint32_t ad = sa + (uint32_t)((((wm*32 + mt*16 + (lane&15))*GS_A_STRIDE)
                                  + s*8 + ((lane>>4)&1)*4)*4);
                ldsm4(af[mt], ad);
            }
            #pragma unroll
            for (int nt=0;nt<4;nt++){
                uint32_t bd = sb + (uint32_t)((((s*16 + (lane&7) + ((lane>>3)&1)*8)*GS_B_STRIDE)
                                  + wn*32 + nt*8 + ((lane>>4)&1)*4)*4);
                ldsm4t(bfr[nt], bd);
            }
            #pragma unroll
            for (int mt=0;mt<2;mt++)
                #pragma unroll
                for (int j=0;j<8;j++)
                    mma_bf16(acc[mt][j], af[mt], bfr[j>>1][(j&1)*2], bfr[j>>1][(j&1)*2+1]);
        }
    }

    int g = lane >> 2, tg = lane & 3;
    #pragma unroll
    for (int mt=0; mt<2; mt++){
        int r0 = bm*128 + wm*32 + mt*16 + g;
        #pragma unroll
        for (int j=0; j<8; j++){
            int col = bn*128 + wn*64 + j*8 + tg*2;
            size_t o0 = (size_t)r0*1024 + col;
            size_t o1 = o0 + (size_t)8*1024;
            float2 v0 = make_float2(acc[mt][j][0], acc[mt][j][1]);
            float2 v1 = make_float2(acc[mt][j][2], acc[mt][j][3]);
            if (mode){
                float2 q0 = *(const float2*)&R[o0];
                float2 q1 = *(const float2*)&R[o1];
                v0.x += q0.x; v0.y += q0.y; v1.x += q1.x; v1.y += q1.y;
            }
            *(float2*)&C[o0] = v0;
            *(float2*)&C[o1] = v1;
        }
    }
}

// ================= per-chunk prep (ratio-table decay, bf16 outputs) =================
#define WKS 68
#define PREP_SMEM ((65*WKS + 4096 + 4096 + 64*5 + 8)*4)

__global__ __launch_bounds__(256) void prep_kernel(const float* __restrict__ x)
{
    extern __shared__ float sm[];
    float* WK    = sm;
    float* Gm    = WK + 65*WKS;
    float* Mb    = Gm + 4096;
    float* cum   = Mb + 4096;
    float* dexpv = cum + 64;
    float* betav = dexpv + 64;
    float* exv   = betav + 64;
    float* rexv  = exv + 64;

    int cid = blockIdx.x;
    int b = cid / (H_*N_);
    int h = (cid / N_) % H_;
    int n = cid % N_;
    int t = threadIdx.x;
    size_t xbase = ((size_t)b*T_ + (size_t)n*C_)*D_ + (size_t)h*64;
    size_t base  = (size_t)cid*4096;

    for (int f = t; f < 65*16; f += 256){
        int r = f >> 4, j4 = (f & 15)*4;
        float4 v;
        if (r == 0 && n == 0) v = make_float4(0.f,0.f,0.f,0.f);
        else v = *(const float4*)&x[xbase + ((size_t)r-1)*D_ + j4];
        *(float4*)&WK[r*WKS + j4] = v;
    }
    if (t < 64){
        int tok = (b*T_ + n*C_ + t)*H_ + h;
        betav[t] = g_beta[tok];
        cum[t]   = g_dec[tok];
    }
    __syncthreads();

    if (t < 65){
        float s = 0.f;
        #pragma unroll
        for (int q=0;q<16;q++){
            float4 v = *(float4*)&WK[t*WKS + q*4];
            s += v.x*v.x + v.y*v.y + v.z*v.z + v.w*v.w;
        }
        float inv = 1.f/fmaxf(sqrtf(s), 1e-12f);
        #pragma unroll
        for (int q=0;q<16;q++){
            float4 v = *(float4*)&WK[t*WKS + q*4];
            v.x*=inv; v.y*=inv; v.z*=inv; v.w*=inv;
            *(float4*)&WK[t*WKS + q*4] = v;
        }
    }
    if (t == 65){
        float s = 0.f;
        for (int c=0;c<64;c++){ s += cum[c]; cum[c] = s; }
    }
    __syncthreads();
    if (t < 64){
        float mid = cum[31];
        dexpv[t] = __expf(cum[t]);
        exv[t]   = __expf(cum[t] - mid);
        rexv[t]  = __expf(mid - cum[t]);
    }

    for (int f = t; f < 1024; f += 256){
        int i = f >> 4, j4 = (f & 15)*4;
        float4 v = *(const float4*)&g_v[xbase + (size_t)i*D_ + j4];
        float bt = betav[i];
        v.x*=bt; v.y*=bt; v.z*=bt; v.w*=bt;
        *(float4*)&Gm[i*64 + j4] = v;
    }
    __syncthreads();

    float y[64];
    if (t < 128){
        if (t < 64){
            #pragma unroll
            for (int i=0;i<64;i++) y[i] = Gm[i*64 + t];
        } else {
            int jj = t - 64;
            #pragma unroll
            for (int i=0;i<64;i++) y[i] = WK[i*WKS + jj]*betav[i]*dexpv[i];
        }
    }
    __syncthreads();

    {
        int tr = (t >> 4)*4, tc = (t & 15)*4;
        float d[4][4];
        #pragma unroll
        for (int a=0;a<4;a++)
            #pragma unroll
            for (int c=0;c<4;c++) d[a][c]=0.f;
        for (int m4=0; m4<64; m4+=4){
            float4 av[4], cv[4];
            #pragma unroll
            for (int a=0;a<4;a++) av[a] = *(float4*)&WK[(tr+a+1)*WKS + m4];
            #pragma unroll
            for (int c=0;c<4;c++) cv[c] = *(float4*)&WK[(tc+c)*WKS + m4];
            #pragma unroll
            for (int a=0;a<4;a++)
                #pragma unroll
                for (int c=0;c<4;c++)
                    d[a][c] += av[a].x*cv[c].x + av[a].y*cv[c].y
                             + av[a].z*cv[c].z + av[a].w*cv[c].w;
        }
        __syncthreads();
        #pragma unroll
        for (int a=0;a<4;a++)
            #pragma unroll
            for (int c=0;c<4;c++)
                Gm[(tr+a)*64 + tc+c] = d[a][c];
    }
    __syncthreads();

    for (int f = t; f < 4096; f += 256){
        int i = f >> 6, j = f & 63;
        Mb[f] = (j < i) ? (-betav[i]*exv[i]*rexv[j]*Gm[(i-1)*64 + j]) : 0.f;
    }
    __syncthreads();

    if (t < 128){
        #pragma unroll
        for (int kb=0; kb<64; kb+=4){
            y[kb+1] = fmaf(Mb[(kb+1)*64+kb],   y[kb],   y[kb+1]);
            y[kb+2] = fmaf(Mb[(kb+2)*64+kb],   y[kb],   y[kb+2]);
            y[kb+2] = fmaf(Mb[(kb+2)*64+kb+1], y[kb+1], y[kb+2]);
            y[kb+3] = fmaf(Mb[(kb+3)*64+kb],   y[kb],   y[kb+3]);
            y[kb+3] = fmaf(Mb[(kb+3)*64+kb+1], y[kb+1], y[kb+3]);
            y[kb+3] = fmaf(Mb[(kb+3)*64+kb+2], y[kb+2], y[kb+3]);
            #pragma unroll
            for (int i=kb+4; i<64; i++){
                float4 m = *(float4*)&Mb[i*64 + kb];
                y[i] = fmaf(m.x, y[kb],
                       fmaf(m.y, y[kb+1],
                       fmaf(m.z, y[kb+2],
                       fmaf(m.w, y[kb+3], y[i]))));
            }
        }
        if (t < 64){
            #pragma unroll
            for (int i=0;i<64;i++) g_vc[base + i*64 + t] = __float2bfloat16(y[i]);
        } else {
            int jj = t - 64;
            #pragma unroll
            for (int i=0;i<64;i++) g_wkcd[base + i*64 + jj] = __float2bfloat16(-y[i]);
        }
    } else {
        int tt = t - 128;
        for (int f = tt; f < 4096; f += 128){
            int i = f >> 6, j = f & 63;
            g_intra[base + f] = __float2bfloat16(
                (i >= j) ? (exv[i]*rexv[j]*Gm[f]) : 0.f);
        }
        for (int f = tt; f < 1024; f += 128){
            int i = f >> 4, j4 = (f & 15)*4;
            float4 v = *(float4*)&WK[(i+1)*WKS + j4];
            float dv = dexpv[i];
            __nv_bfloat162 lo = __floats2bfloat162_rn(v.x*dv, v.y*dv);
            __nv_bfloat162 hi = __floats2bfloat162_rn(v.z*dv, v.w*dv);
            uint2 pkd = make_uint2(*(unsigned*)&lo, *(unsigned*)&hi);
            *(uint2*)&g_rkd[base + i*64 + j4] = pkd;
        }
        float ex63 = exv[63];
        for (int f = tt; f < 4096; f += 128){
            int jt = f >> 6, ct = f & 63;
            g_wkdw[base + f] = __float2bfloat16(
                WK[ct*WKS + jt]*(ex63*rexv[ct]));
        }
        if (t == 128) g_elast[cid] = __expf(cum[63]);
    }
}

// ================= scan: merged S-pass + deferred norm clip =================
#define SS 36
#define OFF_S     0
#define OFF_VN    9216
#define OFF_VC    18432
#define OFF_W     28672
#define OFF_GATE  102400
#define OFF_MISC  102912
#define SCAN_SMEM 103040
#define W_BUF     36864
#define W_TILE    9216

__global__ __launch_bounds__(256) __cluster_dims__(2,1,1) void scan_kernel()
{
    extern __shared__ float sm[];
    char* smc = (char*)sm;
    float* S     = (float*)(smc + OFF_S);
    float* VN    = (float*)(smc + OFF_VN);
    float* gatev = (float*)(smc + OFF_GATE);
    float* misc  = (float*)(smc + OFF_MISC);

    int bid = blockIdx.x;
    int bh = bid >> 1, half = bid & 1;
    int b = bh >> 4, h = bh & 15;
    int t = threadIdx.x;
    int lane = t & 31, w = t >> 5;
    int ebl = (t & 7) * 4;
    int cbl = (t >> 3) * 2;

    uint32_t sb_u32 = smem_u32(sm);
    uint32_t exch_addr = smem_u32(&misc[12]);
    uint32_t peer = half ^ 1;

    for (int i=t; i<2304; i+=256) S[i]=0.f;
    __syncthreads();

    auto prefetch = [&](int n){
        int p = n & 1;
        size_t gb = ((size_t)bh*64 + n)*4096;
        uint32_t wb = sb_u32 + OFF_W + (uint32_t)p*W_BUF;
        #pragma unroll
        for (int u=0; u<2; u++){
            int q = u*256 + t;
            int row = q >> 3, ch = q & 7;
            uint32_t doff = (uint32_t)(row*144 + ch*16);
            size_t goff = gb + row*64 + ch*8;
            cpa16(wb + 0*W_TILE + doff, g_wkcd  + goff);
            cpa16(wb + 1*W_TILE + doff, g_rkd   + goff);
            cpa16(wb + 2*W_TILE + doff, g_intra + goff);
            cpa16(wb + 3*W_TILE + doff, g_wkdw  + goff);
        }
        {
            int row = t >> 2, ch = t & 3;
            cpa16(sb_u32 + OFF_VC + (uint32_t)(p*5120 + row*80 + ch*16),
                  g_vc + gb + row*64 + half*32 + ch*8);
        }
        if (t < 64)
            cpa4(sb_u32 + OFF_GATE + (uint32_t)(p*256 + t*4),
                 g_gate + ((size_t)b*T_ + n*64 + t)*H_ + h);
        if (t == 0)
            cpa4(sb_u32 + OFF_MISC + (uint32_t)((8+p)*4), g_elast + bh*64 + n);
    };

    prefetch(0); asm volatile("cp.async.commit_group;" ::: "memory");

    float fprev = 1.f;

    for (int n=0; n<64; n++){
        int p = n & 1;
        if (n+1 < 64){
            prefetch(n+1);
            asm volatile("cp.async.commit_group;" ::: "memory");
            asm volatile("cp.async.wait_group 1;" ::: "memory");
        } else {
            asm volatile("cp.async.wait_group 0;" ::: "memory");
        }
        __syncthreads();

        const __nv_bfloat16* VC    = (const __nv_bfloat16*)(smc + OFF_VC + p*5120);
        const __nv_bfloat16* WKCD  = (const __nv_bfloat16*)(smc + OFF_W + p*W_BUF);
        const __nv_bfloat16* RKD   = (const __nv_bfloat16*)(smc + OFF_W + p*W_BUF + W_TILE);
        const __nv_bfloat16* INTRA = (const __nv_bfloat16*)(smc + OFF_W + p*W_BUF + 2*W_TILE);
        const __nv_bfloat16* WKDW  = (const __nv_bfloat16*)(smc + OFF_W + p*W_BUF + 3*W_TILE);

        // merged S-pass: macc = (-wkcd)@S' ; oas = rkd@S'
        u64 macc[2][2] = {{0ull,0ull},{0ull,0ull}};
        u64 oas[2][2]  = {{0ull,0ull},{0ull,0ull}};
        {
            #pragma unroll 4
            for (int k4=0;k4<64;k4+=4){
                u64x2 s0 = *(u64x2*)&S[(k4+0)*SS + ebl];
                u64x2 s1 = *(u64x2*)&S[(k4+1)*SS + ebl];
                u64x2 s2 = *(u64x2*)&S[(k4+2)*SS + ebl];
                u64x2 s3 = *(u64x2*)&S[(k4+3)*SS + ebl];
                #pragma unroll
                for (int ci=0;ci<2;ci++){
                    float4 wv = ld4bf(&WKCD[(cbl+ci)*72 + k4]);
                    u64 ww;
                    ww = pk2(wv.x); fma2(macc[ci][0], ww, s0.a); fma2(macc[ci][1], ww, s0.b);
                    ww = pk2(wv.y); fma2(macc[ci][0], ww, s1.a); fma2(macc[ci][1], ww, s1.b);
                    ww = pk2(wv.z); fma2(macc[ci][0], ww, s2.a); fma2(macc[ci][1], ww, s2.b);
                    ww = pk2(wv.w); fma2(macc[ci][0], ww, s3.a); fma2(macc[ci][1], ww, s3.b);
                    float4 rv = ld4bf(&RKD[(cbl+ci)*72 + k4]);
                    ww = pk2(rv.x); fma2(oas[ci][0], ww, s0.a); fma2(oas[ci][1], ww, s0.b);
                    ww = pk2(rv.y); fma2(oas[ci][0], ww, s1.a); fma2(oas[ci][1], ww, s1.b);
                    ww = pk2(rv.z); fma2(oas[ci][0], ww, s2.a); fma2(oas[ci][1], ww, s2.b);
                    ww = pk2(rv.w); fma2(oas[ci][0], ww, s3.a); fma2(oas[ci][1], ww, s3.b);
                }
            }
            // v_new = vc + fprev*macc
            #pragma unroll
            for (int ci=0;ci<2;ci++){
                float4 vcv = ld4bf(&VC[(cbl+ci)*40 + ebl]);
                float2 m0 = up2(macc[ci][0]), m1 = up2(macc[ci][1]);
                u64x2 o;
                o.a = pkf2(fmaf(fprev, m0.x, vcv.x), fmaf(fprev, m0.y, vcv.y));
                o.b = pkf2(fmaf(fprev, m1.x, vcv.z), fmaf(fprev, m1.y, vcv.w));
                *(u64x2*)&VN[(cbl+ci)*SS + ebl] = o;
            }
        }
        __syncthreads();

        // VN-pass: oav = intra@VN ; ud = wkdw@VN
        u64 oav[2][2] = {{0ull,0ull},{0ull,0ull}};
        u64 ud[2][2]  = {{0ull,0ull},{0ull,0ull}};
        {
            #pragma unroll 4
            for (int k4=0;k4<64;k4+=4){
                u64x2 v0 = *(u64x2*)&VN[(k4+0)*SS + ebl];
                u64x2 v1 = *(u64x2*)&VN[(k4+1)*SS + ebl];
                u64x2 v2 = *(u64x2*)&VN[(k4+2)*SS + ebl];
                u64x2 v3 = *(u64x2*)&VN[(k4+3)*SS + ebl];
                #pragma unroll
                for (int ci=0;ci<2;ci++){
                    float4 wv = ld4bf(&INTRA[(cbl+ci)*72 + k4]);
                    u64 ww;
                    ww = pk2(wv.x); fma2(oav[ci][0], ww, v0.a); fma2(oav[ci][1], ww, v0.b);
                    ww = pk2(wv.y); fma2(oav[ci][0], ww, v1.a); fma2(oav[ci][1], ww, v1.b);
                    ww = pk2(wv.z); fma2(oav[ci][0], ww, v2.a); fma2(oav[ci][1], ww, v2.b);
                    ww = pk2(wv.w); fma2(oav[ci][0], ww, v3.a); fma2(oav[ci][1], ww, v3.b);
                }
                #pragma unroll
                for (int di=0;di<2;di++){
                    float4 wd = ld4bf(&WKDW[(cbl+di)*72 + k4]);
                    u64 ww;
                    ww = pk2(wd.x); fma2(ud[di][0], ww, v0.a); fma2(ud[di][1], ww, v0.b);
                    ww = pk2(wd.y); fma2(ud[di][0], ww, v1.a); fma2(ud[di][1], ww, v1.b);
                    ww = pk2(wd.z); fma2(ud[di][0], ww, v2.a); fma2(ud[di][1], ww, v2.b);
                    ww = pk2(wd.w); fma2(ud[di][0], ww, v3.a); fma2(ud[di][1], ww, v3.b);
                }
            }
            // o = fprev*oas + oav ; gated output
            #pragma unroll
            for (int ci=0;ci<2;ci++){
                float gt = gatev[p*64 + cbl+ci];
                float2 s0 = up2(oas[ci][0]), s1 = up2(oas[ci][1]);
                float2 q0 = up2(oav[ci][0]), q1 = up2(oav[ci][1]);
                float o0 = fmaf(fprev, s0.x, q0.x);
                float o1 = fmaf(fprev, s0.y, q0.y);
                float o2 = fmaf(fprev, s1.x, q1.x);
                float o3 = fmaf(fprev, s1.y, q1.y);
                __nv_bfloat162 b0 = __floats2bfloat162_rn(o0*gt, o1*gt);
                __nv_bfloat162 b1 = __floats2bfloat162_rn(o2*gt, o3*gt);
                size_t orow = ((size_t)b*T_ + n*64 + cbl+ci)*D_ + (size_t)h*64 + half*32 + ebl;
                *(__nv_bfloat162*)&g_ogb[orow]   = b0;
                *(__nv_bfloat162*)&g_ogb[orow+2] = b1;
            }
        }
        __syncthreads();

        // S' = S'*(el*fprev) + upd  (pre-clip state) ; Frobenius partial
        float el = misc[8 + p] * fprev;
        float partial = 0.f;
        #pragma unroll
        for (int di=0;di<2;di++){
            float2 u0 = up2(ud[di][0]), u1 = up2(ud[di][1]);
            float uu[4] = {u0.x, u0.y, u1.x, u1.y};
            #pragma unroll
            for (int ei=0;ei<4;ei++){
                int idx = (cbl+di)*SS + ebl + ei;
                float sv = fmaf(S[idx], el, uu[ei]);
                S[idx] = sv;
                partial = fmaf(sv, sv, partial);
            }
        }
        #pragma unroll
        for (int off=16; off>0; off>>=1) partial += __shfl_down_sync(0xffffffffu, partial, off);
        if (lane==0) misc[w] = partial;
        __syncthreads();
        if (t==0){
            float s=0.f;
            #pragma unroll
            for (int i=0;i<8;i++) s += misc[i];
            misc[10] = s;
            uint32_t remote;
            asm volatile("mapa.shared::cluster.u32 %0, %1, %2;" : "=r"(remote)
                         : "r"(exch_addr + (n&1)*4), "r"(peer));
            asm volatile("st.shared::cluster.f32 [%0], %1;" :: "r"(remote), "f"(s) : "memory");
        }
        asm volatile("barrier.cluster.arrive.aligned;" ::: "memory");
        asm volatile("barrier.cluster.wait.aligned;" ::: "memory");
        float total = misc[10] + misc[12 + (n&1)];
        float nrm = sqrtf(total);
        fprev = fminf(nrm,100.f)/fmaxf(nrm,1e-6f);
    }
}

extern "C" void kernel_launch(void* const* d_in, const int* in_sizes, int n_in,
                              void* d_out, int out_size) {
    const float* x      = (const float*)d_in[0];
    const float* w_wr   = (const float*)d_in[1];
    const float* w_gate = (const float*)d_in[2];
    const float* w_out  = (const float*)d_in[3];
    const float* w_beta = (const float*)d_in[4];
    const float* w_alph = (const float*)d_in[5];
    const float* dtb    = (const float*)d_in[6];
    const float* alog   = (const float*)d_in[7];
    float* out = (float*)d_out;

    cudaFuncSetAttribute(proj_kernel, cudaFuncAttributeMaxDynamicSharedMemorySize, PROJ_SMEM);
    cudaFuncSetAttribute(prep_kernel, cudaFuncAttributeMaxDynamicSharedMemorySize, PREP_SMEM);
    cudaFuncSetAttribute(scan_kernel, cudaFuncAttributeMaxDynamicSharedMemorySize, SCAN_SMEM);
    cudaFuncSetAttribute(hgemm,       cudaFuncAttributeMaxDynamicSharedMemorySize, G_SMEM);

    __nv_bfloat16 *xb, *ogb, *wb0, *wb1;
    cudaGetSymbolAddress((void**)&xb,  g_xb);
    cudaGetSymbolAddress((void**)&ogb, g_ogb);
    cudaGetSymbolAddress((void**)&wb0, g_wb0);
    cudaGetSymbolAddress((void**)&wb1, g_wb1);
    float* gv; cudaGetSymbolAddress((void**)&gv, g_v);

    proj_kernel<<<128, 256, PROJ_SMEM>>>(x, w_gate, w_beta, w_alph, dtb, alog);
    cvt_kernel<<<(BT_*D_/4 + 255)/256, 256>>>(x, xb, BT_*D_/4);
    cvt_kernel<<<(D_*D_/4 + 255)/256, 256>>>(w_wr, wb0, D_*D_/4);
    cvt_kernel<<<(D_*D_/4 + 255)/256, 256>>>(w_out, wb1, D_*D_/4);
    hgemm<<<dim3(8,128), 256, G_SMEM>>>(xb, wb0, nullptr, gv, 0);
    prep_kernel<<<BHN_, 256, PREP_SMEM>>>(x);
    scan_kernel<<<128, 256, SCAN_SMEM>>>();
    hgemm<<<dim3(8,128), 256, G_SMEM>>>(ogb, wb1, x, out, 1);
}

// round 16
// speedup vs baseline: 1.4835x; 1.4835x over previous
#include <cuda_runtime.h>
#include <cuda_bf16.h>
#include <math.h>
#include <stdint.h>

#define B_ 4
#define T_ 4096
#define D_ 1024
#define H_ 16
#define C_ 64
#define N_ 64
#define BT_ (B_*T_)
#define BHN_ (B_*H_*N_)

typedef unsigned long long u64;
struct alignas(16) u64x2 { u64 a, b; };

// ---------- scratch ----------
__device__ float g_v[BT_*D_];
__device__ float g_gate[BT_*H_];
__device__ float g_beta[BT_*H_];
__device__ float g_dec[BT_*H_];
__device__ __nv_bfloat16 g_rkd[BHN_*4096];
__device__ __nv_bfloat16 g_wkcd[BHN_*4096];   // NEGATED
__device__ __nv_bfloat16 g_vc[BHN_*4096];
__device__ __nv_bfloat16 g_wkdw[BHN_*4096];   // TRANSPOSED [d][token]
__device__ __nv_bfloat16 g_intra[BHN_*4096];
__device__ float g_elast[BHN_];
__device__ __nv_bfloat16 g_xb[BT_*D_];
__device__ __nv_bfloat16 g_ogb[BT_*D_];
__device__ __nv_bfloat16 g_wb0[D_*D_];
__device__ __nv_bfloat16 g_wb1[D_*D_];

__device__ __forceinline__ uint32_t smem_u32(const void* p){
    uint32_t a;
    asm("{ .reg .u64 t; cvta.to.shared.u64 t, %1; cvt.u32.u64 %0, t; }" : "=r"(a) : "l"(p));
    return a;
}
__device__ __forceinline__ u64 pk2(float x){
    u64 r; asm("mov.b64 %0, {%1,%1};" : "=l"(r) : "f"(x)); return r;
}
__device__ __forceinline__ u64 pkf2(float x, float y){
    u64 r; asm("mov.b64 %0, {%1,%2};" : "=l"(r) : "f"(x), "f"(y)); return r;
}
__device__ __forceinline__ void fma2(u64& d, u64 a, u64 b){
    asm("fma.rn.f32x2 %0, %1, %2, %0;" : "+l"(d) : "l"(a), "l"(b));
}
__device__ __forceinline__ float2 up2(u64 v){
    float2 f; asm("mov.b64 {%0,%1}, %2;" : "=f"(f.x), "=f"(f.y) : "l"(v)); return f;
}
__device__ __forceinline__ void cpa16(uint32_t d, const void* s){
    asm volatile("cp.async.cg.shared.global [%0], [%1], 16;" :: "r"(d), "l"(s));
}
__device__ __forceinline__ void cpa4(uint32_t d, const void* s){
    asm volatile("cp.async.ca.shared.global [%0], [%1], 4;" :: "r"(d), "l"(s));
}
__device__ __forceinline__ float4 ld4bf(const __nv_bfloat16* p){
    u64 raw = *(const u64*)p;
    unsigned lo = (unsigned)raw, hi = (unsigned)(raw>>32);
    float2 a = __bfloat1622float2(*(__nv_bfloat162*)&lo);
    float2 c = __bfloat1622float2(*(__nv_bfloat162*)&hi);
    return make_float4(a.x, a.y, c.x, c.y);
}

// ---------------- fp32 -> bf16 convert ----------------
__global__ __launch_bounds__(256) void cvt_kernel(const float* __restrict__ in,
                                                  __nv_bfloat16* __restrict__ out, int n4)
{
    int i = blockIdx.x*256 + threadIdx.x;
    if (i < n4){
        float4 v = ((const float4*)in)[i];
        __nv_bfloat162 a = __floats2bfloat162_rn(v.x, v.y);
        __nv_bfloat162 b = __floats2bfloat162_rn(v.z, v.w);
        ((__nv_bfloat162*)out)[2*i]   = a;
        ((__nv_bfloat162*)out)[2*i+1] = b;
    }
}

// ================= projections =================
#define XS_STRIDE 132
#define PROJ_SMEM ((128*XS_STRIDE + 128*48)*4)
__global__ __launch_bounds__(256) void proj_kernel(
    const float* __restrict__ x, const float* __restrict__ wg,
    const float* __restrict__ wb, const float* __restrict__ wa,
    const float* __restrict__ dtb, const float* __restrict__ alog)
{
    extern __shared__ float psm[];
    float* Xs = psm;
    float* Ws = psm + 128*XS_STRIDE;
    int t = threadIdx.x;
    int row = t & 127, og = t >> 7;
    int o0 = og*24;
    int r0 = blockIdx.x * 128;

    float acc[24];
    #pragma unroll
    for (int j=0;j<24;j++) acc[j]=0.f;

    for (int k0=0; k0<1024; k0+=128){
        #pragma unroll
        for (int i=0;i<16;i++){
            int f4 = i*256 + t;
            int m = f4 >> 5, kv = (f4 & 31)*4;
            float4 v = *(const float4*)&x[(size_t)(r0+m)*1024 + k0 + kv];
            *(float4*)&Xs[m*XS_STRIDE + kv] = v;
        }
        for (int e = t; e < 128*48; e += 256){
            int kk = e / 48, o = e % 48;
            const float* W = (o<16) ? wg : ((o<32) ? wb : wa);
            Ws[kk*48 + o] = W[(size_t)(k0+kk)*16 + (o & 15)];
        }
        __syncthreads();
        #pragma unroll 4
        for (int kk=0; kk<128; kk++){
            float xv = Xs[row*XS_STRIDE + kk];
            const float* wrow = &Ws[kk*48 + o0];
            #pragma unroll
            for (int j=0;j<24;j+=4){
                float4 w4 = *(const float4*)&wrow[j];
                acc[j]   += xv*w4.x; acc[j+1] += xv*w4.y;
                acc[j+2] += xv*w4.z; acc[j+3] += xv*w4.w;
            }
        }
        __syncthreads();
    }
    int rg = r0 + row;
    #pragma unroll
    for (int j=0;j<24;j++){
        int o = o0 + j;
        int h = o & 15, kind = o >> 4;
        float s = acc[j];
        if (kind==0)      g_gate[rg*16+h] = 1.f/(1.f+__expf(-s));
        else if (kind==1) g_beta[rg*16+h] = 1.f/(1.f+__expf(-s));
        else {
            float v = s + dtb[h];
            float sp = fmaxf(v,0.f) + log1pf(__expf(-fabsf(v)));
            g_dec[rg*16+h] = -__expf(alog[h])*sp;
        }
    }
}

// ================= bf16 mma GEMM, cp.async 3-stage =================
#define GS_A_STRIDE 20
#define GS_B_STRIDE 68
#define GS_A_TILE  (128*GS_A_STRIDE)
#define GS_B_TILE  (32*GS_B_STRIDE)
#define GS_STAGE   (GS_A_TILE + GS_B_TILE)
#define G_SMEM     (3*GS_STAGE*4)

__device__ __forceinline__ void ldsm4(unsigned r[4], uint32_t a){
    asm volatile("ldmatrix.sync.aligned.m8n8.x4.shared.b16 {%0,%1,%2,%3}, [%4];"
        : "=r"(r[0]),"=r"(r[1]),"=r"(r[2]),"=r"(r[3]) : "r"(a));
}
__device__ __forceinline__ void ldsm4t(unsigned r[4], uint32_t a){
    asm volatile("ldmatrix.sync.aligned.m8n8.x4.trans.shared.b16 {%0,%1,%2,%3}, [%4];"
        : "=r"(r[0]),"=r"(r[1]),"=r"(r[2]),"=r"(r[3]) : "r"(a));
}
__device__ __forceinline__ void mma_bf16(float* c, const unsigned* a, unsigned b0, unsigned b1){
    asm volatile("mma.sync.aligned.m16n8k16.row.col.f32.bf16.bf16.f32 "
      "{%0,%1,%2,%3}, {%4,%5,%6,%7}, {%8,%9}, {%0,%1,%2,%3};"
      : "+f"(c[0]),"+f"(c[1]),"+f"(c[2]),"+f"(c[3])
      : "r"(a[0]),"r"(a[1]),"r"(a[2]),"r"(a[3]),"r"(b0),"r"(b1));
}

__global__ __launch_bounds__(256) void hgemm(
    const __nv_bfloat16* __restrict__ A, const __nv_bfloat16* __restrict__ Bw,
    const float* __restrict__ R, float* __restrict__ C, int mode)
{
    extern __shared__ float gsm[];
    uint32_t sbase = smem_u32(gsm);

    int t = threadIdx.x, lane = t & 31, warp = t >> 5;
    int wm = warp >> 1, wn = warp & 1;
    int bm = blockIdx.y, bn = blockIdx.x;
    const __nv_bfloat16* Ab = A + (size_t)(bm*128)*1024;
    const __nv_bfloat16* Bb = Bw + (size_t)bn*128;

    float acc[2][8][4];
    #pragma unroll
    for (int mt=0;mt<2;mt++)
        #pragma unroll
        for (int j=0;j<8;j++)
            #pragma unroll
            for (int r=0;r<4;r++) acc[mt][j][r]=0.f;

    auto issue = [&](int it){
        uint32_t st = sbase + (uint32_t)(it % 3)*(GS_STAGE*4);
        #pragma unroll
        for (int u=0;u<2;u++){
            int row = u*64 + (t>>2), ch = t&3;
            uint32_t so = st + (uint32_t)((row*GS_A_STRIDE + ch*4)*4);
            cpa16(so, Ab + (size_t)row*1024 + it*32 + ch*8);
        }
        uint32_t sb = st + GS_A_TILE*4;
        #pragma unroll
        for (int u=0;u<2;u++){
            int row = u*16 + (t>>4), ch = t&15;
            uint32_t so = sb + (uint32_t)((row*GS_B_STRIDE + ch*4)*4);
            cpa16(so, Bb + (size_t)(it*32 + row)*1024 + ch*8);
        }
    };

    issue(0); asm volatile("cp.async.commit_group;" ::: "memory");
    issue(1); asm volatile("cp.async.commit_group;" ::: "memory");

    for (int it=0; it<32; it++){
        if (it < 31) asm volatile("cp.async.wait_group 1;" ::: "memory");
        else         asm volatile("cp.async.wait_group 0;" ::: "memory");
        __syncthreads();
        if (it+2 < 32){
            issue(it+2);
            asm volatile("cp.async.commit_group;" ::: "memory");
        }
        uint32_t sa = sbase + (uint32_t)(it % 3)*(GS_STAGE*4);
        uint32_t sb = sa + GS_A_TILE*4;
        #pragma unroll
        for (int s=0;s<2;s++){
            unsigned af[2][4], bfr[4][4];
            #pragma unroll
            for (int mt=0;mt<2;mt++){
                uint32_t ad = sa + (uint32_t)((((wm*32 + mt*16 + (lane&15))*GS_A_STRIDE)
                                  + s*8 + ((lane>>4)&1)*4)*4);
                ldsm4(af[mt], ad);
            }
            #pragma unroll
            for (int nt=0;nt<4;nt++){
                uint32_t bd = sb + (uint32_t)((((s*16 + (lane&7) + ((lane>>3)&1)*8)*GS_B_STRIDE)
                                  + wn*32 + nt*8 + ((lane>>4)&1)*4)*4);
                ldsm4t(bfr[nt], bd);
            }
            #pragma unroll
            for (int mt=0;mt<2;mt++)
                #pragma unroll
                for (int j=0;j<8;j++)
                    mma_bf16(acc[mt][j], af[mt], bfr[j>>1][(j&1)*2], bfr[j>>1][(j&1)*2+1]);
        }
    }

    int g = lane >> 2, tg = lane & 3;
    #pragma unroll
    for (int mt=0; mt<2; mt++){
        int r0 = bm*128 + wm*32 + mt*16 + g;
        #pragma unroll
        for (int j=0; j<8; j++){
            int col = bn*128 + wn*64 + j*8 + tg*2;
            size_t o0 = (size_t)r0*1024 + col;
            size_t o1 = o0 + (size_t)8*1024;
            float2 v0 = make_float2(acc[mt][j][0], acc[mt][j][1]);
            float2 v1 = make_float2(acc[mt][j][2], acc[mt][j][3]);
            if (mode){
                float2 q0 = *(const float2*)&R[o0];
                float2 q1 = *(const float2*)&R[o1];
                v0.x += q0.x; v0.y += q0.y; v1.x += q1.x; v1.y += q1.y;
            }
            *(float2*)&C[o0] = v0;
            *(float2*)&C[o1] = v1;
        }
    }
}

// ================= per-chunk prep (ratio-table decay, bf16 outputs) =================
#define WKS 68
#define PREP_SMEM ((65*WKS + 4096 + 4096 + 64*5 + 8)*4)

__global__ __launch_bounds__(256) void prep_kernel(const float* __restrict__ x)
{
    extern __shared__ float sm[];
    float* WK    = sm;
    float* Gm    = WK + 65*WKS;
    float* Mb    = Gm + 4096;
    float* cum   = Mb + 4096;
    float* dexpv = cum + 64;
    float* betav = dexpv + 64;
    float* exv   = betav + 64;
    float* rexv  = exv + 64;

    int cid = blockIdx.x;
    int b = cid / (H_*N_);
    int h = (cid / N_) % H_;
    int n = cid % N_;
    int t = threadIdx.x;
    size_t xbase = ((size_t)b*T_ + (size_t)n*C_)*D_ + (size_t)h*64;
    size_t base  = (size_t)cid*4096;

    for (int f = t; f < 65*16; f += 256){
        int r = f >> 4, j4 = (f & 15)*4;
        float4 v;
        if (r == 0 && n == 0) v = make_float4(0.f,0.f,0.f,0.f);
        else v = *(const float4*)&x[xbase + ((size_t)r-1)*D_ + j4];
        *(float4*)&WK[r*WKS + j4] = v;
    }
    if (t < 64){
        int tok = (b*T_ + n*C_ + t)*H_ + h;
        betav[t] = g_beta[tok];
        cum[t]   = g_dec[tok];
    }
    __syncthreads();

    if (t < 65){
        float s = 0.f;
        #pragma unroll
        for (int q=0;q<16;q++){
            float4 v = *(float4*)&WK[t*WKS + q*4];
            s += v.x*v.x + v.y*v.y + v.z*v.z + v.w*v.w;
        }
        float inv = 1.f/fmaxf(sqrtf(s), 1e-12f);
        #pragma unroll
        for (int q=0;q<16;q++){
            float4 v = *(float4*)&WK[t*WKS + q*4];
            v.x*=inv; v.y*=inv; v.z*=inv; v.w*=inv;
            *(float4*)&WK[t*WKS + q*4] = v;
        }
    }
    if (t == 65){
        float s = 0.f;
        for (int c=0;c<64;c++){ s += cum[c]; cum[c] = s; }
    }
    __syncthreads();
    if (t < 64){
        float mid = cum[31];
        dexpv[t] = __expf(cum[t]);
        exv[t]   = __expf(cum[t] - mid);
        rexv[t]  = __expf(mid - cum[t]);
    }

    for (int f = t; f < 1024; f += 256){
        int i = f >> 4, j4 = (f & 15)*4;
        float4 v = *(const float4*)&g_v[xbase + (size_t)i*D_ + j4];
        float bt = betav[i];
        v.x*=bt; v.y*=bt; v.z*=bt; v.w*=bt;
        *(float4*)&Gm[i*64 + j4] = v;
    }
    __syncthreads();

    float y[64];
    if (t < 128){
        if (t < 64){
            #pragma unroll
            for (int i=0;i<64;i++) y[i] = Gm[i*64 + t];
        } else {
            int jj = t - 64;
            #pragma unroll
            for (int i=0;i<64;i++) y[i] = WK[i*WKS + jj]*betav[i]*dexpv[i];
        }
    }
    __syncthreads();

    {
        int tr = (t >> 4)*4, tc = (t & 15)*4;
        float d[4][4];
        #pragma unroll
        for (int a=0;a<4;a++)
            #pragma unroll
            for (int c=0;c<4;c++) d[a][c]=0.f;
        for (int m4=0; m4<64; m4+=4){
            float4 av[4], cv[4];
            #pragma unroll
            for (int a=0;a<4;a++) av[a] = *(float4*)&WK[(tr+a+1)*WKS + m4];
            #pragma unroll
            for (int c=0;c<4;c++) cv[c] = *(float4*)&WK[(tc+c)*WKS + m4];
            #pragma unroll
            for (int a=0;a<4;a++)
                #pragma unroll
                for (int c=0;c<4;c++)
                    d[a][c] += av[a].x*cv[c].x + av[a].y*cv[c].y
                             + av[a].z*cv[c].z + av[a].w*cv[c].w;
        }
        __syncthreads();
        #pragma unroll
        for (int a=0;a<4;a++)
            #pragma unroll
            for (int c=0;c<4;c++)
                Gm[(tr+a)*64 + tc+c] = d[a][c];
    }
    __syncthreads();

    for (int f = t; f < 4096; f += 256){
        int i = f >> 6, j = f & 63;
        Mb[f] = (j < i) ? (-betav[i]*exv[i]*rexv[j]*Gm[(i-1)*64 + j]) : 0.f;
    }
    __syncthreads();

    if (t < 128){
        #pragma unroll
        for (int kb=0; kb<64; kb+=4){
            y[kb+1] = fmaf(Mb[(kb+1)*64+kb],   y[kb],   y[kb+1]);
            y[kb+2] = fmaf(Mb[(kb+2)*64+kb],   y[kb],   y[kb+2]);
            y[kb+2] = fmaf(Mb[(kb+2)*64+kb+1], y[kb+1], y[kb+2]);
            y[kb+3] = fmaf(Mb[(kb+3)*64+kb],   y[kb],   y[kb+3]);
            y[kb+3] = fmaf(Mb[(kb+3)*64+kb+1], y[kb+1], y[kb+3]);
            y[kb+3] = fmaf(Mb[(kb+3)*64+kb+2], y[kb+2], y[kb+3]);
            #pragma unroll
            for (int i=kb+4; i<64; i++){
                float4 m = *(float4*)&Mb[i*64 + kb];
                y[i] = fmaf(m.x, y[kb],
                       fmaf(m.y, y[kb+1],
                       fmaf(m.z, y[kb+2],
                       fmaf(m.w, y[kb+3], y[i]))));
            }
        }
        if (t < 64){
            #pragma unroll
            for (int i=0;i<64;i++) g_vc[base + i*64 + t] = __float2bfloat16(y[i]);
        } else {
            int jj = t - 64;
            #pragma unroll
            for (int i=0;i<64;i++) g_wkcd[base + i*64 + jj] = __float2bfloat16(-y[i]);
        }
    } else {
        int tt = t - 128;
        for (int f = tt; f < 4096; f += 128){
            int i = f >> 6, j = f & 63;
            g_intra[base + f] = __float2bfloat16(
                (i >= j) ? (exv[i]*rexv[j]*Gm[f]) : 0.f);
        }
        for (int f = tt; f < 1024; f += 128){
            int i = f >> 4, j4 = (f & 15)*4;
            float4 v = *(float4*)&WK[(i+1)*WKS + j4];
            float dv = dexpv[i];
            __nv_bfloat162 lo = __floats2bfloat162_rn(v.x*dv, v.y*dv);
            __nv_bfloat162 hi = __floats2bfloat162_rn(v.z*dv, v.w*dv);
            uint2 pkd = make_uint2(*(unsigned*)&lo, *(unsigned*)&hi);
            *(uint2*)&g_rkd[base + i*64 + j4] = pkd;
        }
        float ex63 = exv[63];
        for (int f = tt; f < 4096; f += 128){
            int jt = f >> 6, ct = f & 63;
            g_wkdw[base + f] = __float2bfloat16(
                WK[ct*WKS + jt]*(ex63*rexv[ct]));
        }
        if (t == 128) g_elast[cid] = __expf(cum[63]);
    }
}

// ================= scan: R14 structure + deferred norm clip only =================
#define SS 36
#define OFF_S     0
#define OFF_VN    9216
#define OFF_VC    18432
#define OFF_W     28672
#define OFF_GATE  102400
#define OFF_MISC  102912
#define SCAN_SMEM 103040
#define W_BUF     36864
#define W_TILE    9216

__global__ __launch_bounds__(256) __cluster_dims__(2,1,1) void scan_kernel()
{
    extern __shared__ float sm[];
    char* smc = (char*)sm;
    float* S     = (float*)(smc + OFF_S);
    float* VN    = (float*)(smc + OFF_VN);
    float* gatev = (float*)(smc + OFF_GATE);
    float* misc  = (float*)(smc + OFF_MISC);

    int bid = blockIdx.x;
    int bh = bid >> 1, half = bid & 1;
    int b = bh >> 4, h = bh & 15;
    int t = threadIdx.x;
    int lane = t & 31, w = t >> 5;
    int ebl = (t & 7) * 4;
    int cbl = (t >> 3) * 2;

    uint32_t sb_u32 = smem_u32(sm);
    uint32_t exch_addr = smem_u32(&misc[12]);
    uint32_t peer = half ^ 1;

    for (int i=t; i<2304; i+=256) S[i]=0.f;
    __syncthreads();

    auto prefetch = [&](int n){
        int p = n & 1;
        size_t gb = ((size_t)bh*64 + n)*4096;
        uint32_t wb = sb_u32 + OFF_W + (uint32_t)p*W_BUF;
        #pragma unroll
        for (int u=0; u<2; u++){
            int q = u*256 + t;
            int row = q >> 3, ch = q & 7;
            uint32_t doff = (uint32_t)(row*144 + ch*16);
            size_t goff = gb + row*64 + ch*8;
            cpa16(wb + 0*W_TILE + doff, g_wkcd  + goff);
            cpa16(wb + 1*W_TILE + doff, g_rkd   + goff);
            cpa16(wb + 2*W_TILE + doff, g_intra + goff);
            cpa16(wb + 3*W_TILE + doff, g_wkdw  + goff);
        }
        {
            int row = t >> 2, ch = t & 3;
            cpa16(sb_u32 + OFF_VC + (uint32_t)(p*5120 + row*80 + ch*16),
                  g_vc + gb + row*64 + half*32 + ch*8);
        }
        if (t < 64)
            cpa4(sb_u32 + OFF_GATE + (uint32_t)(p*256 + t*4),
                 g_gate + ((size_t)b*T_ + n*64 + t)*H_ + h);
        if (t == 0)
            cpa4(sb_u32 + OFF_MISC + (uint32_t)((8+p)*4), g_elast + bh*64 + n);
    };

    prefetch(0); asm volatile("cp.async.commit_group;" ::: "memory");

    float fprev = 1.f;

    for (int n=0; n<64; n++){
        int p = n & 1;
        if (n+1 < 64){
            prefetch(n+1);
            asm volatile("cp.async.commit_group;" ::: "memory");
            asm volatile("cp.async.wait_group 1;" ::: "memory");
        } else {
            asm volatile("cp.async.wait_group 0;" ::: "memory");
        }
        __syncthreads();

        const __nv_bfloat16* VC    = (const __nv_bfloat16*)(smc + OFF_VC + p*5120);
        const __nv_bfloat16* WKCD  = (const __nv_bfloat16*)(smc + OFF_W + p*W_BUF);
        const __nv_bfloat16* RKD   = (const __nv_bfloat16*)(smc + OFF_W + p*W_BUF + W_TILE);
        const __nv_bfloat16* INTRA = (const __nv_bfloat16*)(smc + OFF_W + p*W_BUF + 2*W_TILE);
        const __nv_bfloat16* WKDW  = (const __nv_bfloat16*)(smc + OFF_W + p*W_BUF + 3*W_TILE);

        // phase 1: v_new = vc + fprev*((-wkcd) @ S')
        {
            u64 acc[2][2] = {{0ull,0ull},{0ull,0ull}};
            #pragma unroll 4
            for (int k4=0;k4<64;k4+=4){
                u64x2 s0 = *(u64x2*)&S[(k4+0)*SS + ebl];
                u64x2 s1 = *(u64x2*)&S[(k4+1)*SS + ebl];
                u64x2 s2 = *(u64x2*)&S[(k4+2)*SS + ebl];
                u64x2 s3 = *(u64x2*)&S[(k4+3)*SS + ebl];
                #pragma unroll
                for (int ci=0;ci<2;ci++){
                    float4 wv = ld4bf(&WKCD[(cbl+ci)*72 + k4]);
                    u64 ww;
                    ww = pk2(wv.x); fma2(acc[ci][0], ww, s0.a); fma2(acc[ci][1], ww, s0.b);
                    ww = pk2(wv.y); fma2(acc[ci][0], ww, s1.a); fma2(acc[ci][1], ww, s1.b);
                    ww = pk2(wv.z); fma2(acc[ci][0], ww, s2.a); fma2(acc[ci][1], ww, s2.b);
                    ww = pk2(wv.w); fma2(acc[ci][0], ww, s3.a); fma2(acc[ci][1], ww, s3.b);
                }
            }
            #pragma unroll
            for (int ci=0;ci<2;ci++){
                float4 vcv = ld4bf(&VC[(cbl+ci)*40 + ebl]);
                float2 m0 = up2(acc[ci][0]), m1 = up2(acc[ci][1]);
                u64x2 o;
                o.a = pkf2(fmaf(fprev, m0.x, vcv.x), fmaf(fprev, m0.y, vcv.y));
                o.b = pkf2(fmaf(fprev, m1.x, vcv.z), fmaf(fprev, m1.y, vcv.w));
                *(u64x2*)&VN[(cbl+ci)*SS + ebl] = o;
            }
        }
        __syncthreads();

        // phase 2: o = fprev*(rkd@S') + intra@VN ; ud = wkdw@VN
        u64 oa[2][2] = {{0ull,0ull},{0ull,0ull}};
        u64 ud[2][2] = {{0ull,0ull},{0ull,0ull}};
        {
            #pragma unroll 4
            for (int k4=0;k4<64;k4+=4){
                u64x2 s0 = *(u64x2*)&S[(k4+0)*SS + ebl];
                u64x2 s1 = *(u64x2*)&S[(k4+1)*SS + ebl];
                u64x2 s2 = *(u64x2*)&S[(k4+2)*SS + ebl];
                u64x2 s3 = *(u64x2*)&S[(k4+3)*SS + ebl];
                #pragma unroll
                for (int ci=0;ci<2;ci++){
                    float4 wv = ld4bf(&RKD[(cbl+ci)*72 + k4]);
                    u64 ww;
                    ww = pk2(wv.x); fma2(oa[ci][0], ww, s0.a); fma2(oa[ci][1], ww, s0.b);
                    ww = pk2(wv.y); fma2(oa[ci][0], ww, s1.a); fma2(oa[ci][1], ww, s1.b);
                    ww = pk2(wv.z); fma2(oa[ci][0], ww, s2.a); fma2(oa[ci][1], ww, s2.b);
                    ww = pk2(wv.w); fma2(oa[ci][0], ww, s3.a); fma2(oa[ci][1], ww, s3.b);
                }
            }
            // scale by fprev, then accumulate VN terms
            #pragma unroll
            for (int ci=0;ci<2;ci++){
                float2 a0 = up2(oa[ci][0]), a1 = up2(oa[ci][1]);
                oa[ci][0] = pkf2(a0.x*fprev, a0.y*fprev);
                oa[ci][1] = pkf2(a1.x*fprev, a1.y*fprev);
            }
            #pragma unroll 4
            for (int k4=0;k4<64;k4+=4){
                u64x2 v0 = *(u64x2*)&VN[(k4+0)*SS + ebl];
                u64x2 v1 = *(u64x2*)&VN[(k4+1)*SS + ebl];
                u64x2 v2 = *(u64x2*)&VN[(k4+2)*SS + ebl];
                u64x2 v3 = *(u64x2*)&VN[(k4+3)*SS + ebl];
                #pragma unroll
                for (int ci=0;ci<2;ci++){
                    float4 wv = ld4bf(&INTRA[(cbl+ci)*72 + k4]);
                    u64 ww;
                    ww = pk2(wv.x); fma2(oa[ci][0], ww, v0.a); fma2(oa[ci][1], ww, v0.b);
                    ww = pk2(wv.y); fma2(oa[ci][0], ww, v1.a); fma2(oa[ci][1], ww, v1.b);
                    ww = pk2(wv.z); fma2(oa[ci][0], ww, v2.a); fma2(oa[ci][1], ww, v2.b);
                    ww = pk2(wv.w); fma2(oa[ci][0], ww, v3.a); fma2(oa[ci][1], ww, v3.b);
                }
                #pragma unroll
                for (int di=0;di<2;di++){
                    float4 wd = ld4bf(&WKDW[(cbl+di)*72 + k4]);
                    u64 ww;
                    ww = pk2(wd.x); fma2(ud[di][0], ww, v0.a); fma2(ud[di][1], ww, v0.b);
                    ww = pk2(wd.y); fma2(ud[di][0], ww, v1.a); fma2(ud[di][1], ww, v1.b);
                    ww = pk2(wd.z); fma2(ud[di][0], ww, v2.a); fma2(ud[di][1], ww, v2.b);
                    ww = pk2(wd.w); fma2(ud[di][0], ww, v3.a); fma2(ud[di][1], ww, v3.b);
                }
            }
            #pragma unroll
            for (int ci=0;ci<2;ci++){
                float gt = gatev[p*64 + cbl+ci];
                float2 p0 = up2(oa[ci][0]), p1 = up2(oa[ci][1]);
                __nv_bfloat162 b0 = __floats2bfloat162_rn(p0.x*gt, p0.y*gt);
                __nv_bfloat162 b1 = __floats2bfloat162_rn(p1.x*gt, p1.y*gt);
                size_t orow = ((size_t)b*T_ + n*64 + cbl+ci)*D_ + (size_t)h*64 + half*32 + ebl;
                *(__nv_bfloat162*)&g_ogb[orow]   = b0;
                *(__nv_bfloat162*)&g_ogb[orow+2] = b1;
            }
        }
        __syncthreads();

        // S' = S'*(el*fprev) + upd (pre-clip) ; Frobenius partial
        float el = misc[8 + p] * fprev;
        float partial = 0.f;
        #pragma unroll
        for (int di=0;di<2;di++){
            float2 u0 = up2(ud[di][0]), u1 = up2(ud[di][1]);
            float uu[4] = {u0.x, u0.y, u1.x, u1.y};
            #pragma unroll
            for (int ei=0;ei<4;ei++){
                int idx = (cbl+di)*SS + ebl + ei;
                float sv = fmaf(S[idx], el, uu[ei]);
                S[idx] = sv;
                partial = fmaf(sv, sv, partial);
            }
        }
        #pragma unroll
        for (int off=16; off>0; off>>=1) partial += __shfl_down_sync(0xffffffffu, partial, off);
        if (lane==0) misc[w] = partial;
        __syncthreads();
        if (t==0){
            float s=0.f;
            #pragma unroll
            for (int i=0;i<8;i++) s += misc[i];
            misc[10] = s;
            uint32_t remote;
            asm volatile("mapa.shared::cluster.u32 %0, %1, %2;" : "=r"(remote)
                         : "r"(exch_addr + (n&1)*4), "r"(peer));
            asm volatile("st.shared::cluster.f32 [%0], %1;" :: "r"(remote), "f"(s) : "memory");
        }
        asm volatile("barrier.cluster.arrive.aligned;" ::: "memory");
        asm volatile("barrier.cluster.wait.aligned;" ::: "memory");
        float total = misc[10] + misc[12 + (n&1)];
        float nrm = sqrtf(total);
        fprev = fminf(nrm,100.f)/fmaxf(nrm,1e-6f);
    }
}

extern "C" void kernel_launch(void* const* d_in, const int* in_sizes, int n_in,
                              void* d_out, int out_size) {
    const float* x      = (const float*)d_in[0];
    const float* w_wr   = (const float*)d_in[1];
    const float* w_gate = (const float*)d_in[2];
    const float* w_out  = (const float*)d_in[3];
    const float* w_beta = (const float*)d_in[4];
    const float* w_alph = (const float*)d_in[5];
    const float* dtb    = (const float*)d_in[6];
    const float* alog   = (const float*)d_in[7];
    float* out = (float*)d_out;

    cudaFuncSetAttribute(proj_kernel, cudaFuncAttributeMaxDynamicSharedMemorySize, PROJ_SMEM);
    cudaFuncSetAttribute(prep_kernel, cudaFuncAttributeMaxDynamicSharedMemorySize, PREP_SMEM);
    cudaFuncSetAttribute(scan_kernel, cudaFuncAttributeMaxDynamicSharedMemorySize, SCAN_SMEM);
    cudaFuncSetAttribute(hgemm,       cudaFuncAttributeMaxDynamicSharedMemorySize, G_SMEM);

    __nv_bfloat16 *xb, *ogb, *wb0, *wb1;
    cudaGetSymbolAddress((void**)&xb,  g_xb);
    cudaGetSymbolAddress((void**)&ogb, g_ogb);
    cudaGetSymbolAddress((void**)&wb0, g_wb0);
    cudaGetSymbolAddress((void**)&wb1, g_wb1);
    float* gv; cudaGetSymbolAddress((void**)&gv, g_v);

    proj_kernel<<<128, 256, PROJ_SMEM>>>(x, w_gate, w_beta, w_alph, dtb, alog);
    cvt_kernel<<<(BT_*D_/4 + 255)/256, 256>>>(x, xb, BT_*D_/4);
    cvt_kernel<<<(D_*D_/4 + 255)/256, 256>>>(w_wr, wb0, D_*D_/4);
    cvt_kernel<<<(D_*D_/4 + 255)/256, 256>>>(w_out, wb1, D_*D_/4);
    hgemm<<<dim3(8,128), 256, G_SMEM>>>(xb, wb0, nullptr, gv, 0);
    prep_kernel<<<BHN_, 256, PREP_SMEM>>>(x);
    scan_kernel<<<128, 256, SCAN_SMEM>>>();
    hgemm<<<dim3(8,128), 256, G_SMEM>>>(ogb, wb1, x, out, 1);
}

// round 17
// speedup vs baseline: 1.4933x; 1.0066x over previous
#include <cuda_runtime.h>
#include <cuda_bf16.h>
#include <math.h>
#include <stdint.h>

#define B_ 4
#define T_ 4096
#define D_ 1024
#define H_ 16
#define C_ 64
#define N_ 64
#define BT_ (B_*T_)
#define BHN_ (B_*H_*N_)

typedef unsigned long long u64;
struct alignas(16) u64x2 { u64 a, b; };

// ---------- scratch ----------
__device__ __nv_bfloat16 g_vb[BT_*D_];      // x @ w_write (bf16)
__device__ float g_gate[BT_*H_];
__device__ float g_beta[BT_*H_];
__device__ float g_dec[BT_*H_];
__device__ __nv_bfloat16 g_rkd[BHN_*4096];
__device__ __nv_bfloat16 g_wkcd[BHN_*4096];   // NEGATED
__device__ __nv_bfloat16 g_vc[BHN_*4096];
__device__ __nv_bfloat16 g_wkdw[BHN_*4096];   // TRANSPOSED [d][token]
__device__ __nv_bfloat16 g_intra[BHN_*4096];
__device__ float g_elast[BHN_];
__device__ __nv_bfloat16 g_xb[BT_*D_];
__device__ __nv_bfloat16 g_ogb[BT_*D_];
__device__ __nv_bfloat16 g_wb0[D_*D_];
__device__ __nv_bfloat16 g_wb1[D_*D_];

__device__ __forceinline__ uint32_t smem_u32(const void* p){
    uint32_t a;
    asm("{ .reg .u64 t; cvta.to.shared.u64 t, %1; cvt.u32.u64 %0, t; }" : "=r"(a) : "l"(p));
    return a;
}
__device__ __forceinline__ u64 pk2(float x){
    u64 r; asm("mov.b64 %0, {%1,%1};" : "=l"(r) : "f"(x)); return r;
}
__device__ __forceinline__ u64 pkf2(float x, float y){
    u64 r; asm("mov.b64 %0, {%1,%2};" : "=l"(r) : "f"(x), "f"(y)); return r;
}
__device__ __forceinline__ void fma2(u64& d, u64 a, u64 b){
    asm("fma.rn.f32x2 %0, %1, %2, %0;" : "+l"(d) : "l"(a), "l"(b));
}
__device__ __forceinline__ float2 up2(u64 v){
    float2 f; asm("mov.b64 {%0,%1}, %2;" : "=f"(f.x), "=f"(f.y) : "l"(v)); return f;
}
__device__ __forceinline__ void cpa16(uint32_t d, const void* s){
    asm volatile("cp.async.cg.shared.global [%0], [%1], 16;" :: "r"(d), "l"(s));
}
__device__ __forceinline__ void cpa4(uint32_t d, const void* s){
    asm volatile("cp.async.ca.shared.global [%0], [%1], 4;" :: "r"(d), "l"(s));
}
__device__ __forceinline__ float4 ld4bf(const __nv_bfloat16* p){
    u64 raw = *(const u64*)p;
    unsigned lo = (unsigned)raw, hi = (unsigned)(raw>>32);
    float2 a = __bfloat1622float2(*(__nv_bfloat162*)&lo);
    float2 c = __bfloat1622float2(*(__nv_bfloat162*)&hi);
    return make_float4(a.x, a.y, c.x, c.y);
}

// ---------------- fp32 -> bf16 convert (weights only now) ----------------
__global__ __launch_bounds__(256) void cvt_kernel(const float* __restrict__ in,
                                                  __nv_bfloat16* __restrict__ out, int n4)
{
    int i = blockIdx.x*256 + threadIdx.x;
    if (i < n4){
        float4 v = ((const float4*)in)[i];
        __nv_bfloat162 a = __floats2bfloat162_rn(v.x, v.y);
        __nv_bfloat162 b = __floats2bfloat162_rn(v.z, v.w);
        ((__nv_bfloat162*)out)[2*i]   = a;
        ((__nv_bfloat162*)out)[2*i+1] = b;
    }
}

// ================= projections (+ inline x->bf16) =================
#define XS_STRIDE 132
#define PROJ_SMEM ((128*XS_STRIDE + 128*48)*4)
__global__ __launch_bounds__(256) void proj_kernel(
    const float* __restrict__ x, const float* __restrict__ wg,
    const float* __restrict__ wb, const float* __restrict__ wa,
    const float* __restrict__ dtb, const float* __restrict__ alog)
{
    extern __shared__ float psm[];
    float* Xs = psm;
    float* Ws = psm + 128*XS_STRIDE;
    int t = threadIdx.x;
    int row = t & 127, og = t >> 7;
    int o0 = og*24;
    int r0 = blockIdx.x * 128;

    float acc[24];
    #pragma unroll
    for (int j=0;j<24;j++) acc[j]=0.f;

    for (int k0=0; k0<1024; k0+=128){
        #pragma unroll
        for (int i=0;i<16;i++){
            int f4 = i*256 + t;
            int m = f4 >> 5, kv = (f4 & 31)*4;
            float4 v = *(const float4*)&x[(size_t)(r0+m)*1024 + k0 + kv];
            *(float4*)&Xs[m*XS_STRIDE + kv] = v;
            // inline bf16 copy of x
            __nv_bfloat162 lo = __floats2bfloat162_rn(v.x, v.y);
            __nv_bfloat162 hi = __floats2bfloat162_rn(v.z, v.w);
            uint2 pkd = make_uint2(*(unsigned*)&lo, *(unsigned*)&hi);
            *(uint2*)&g_xb[(size_t)(r0+m)*1024 + k0 + kv] = pkd;
        }
        for (int e = t; e < 128*48; e += 256){
            int kk = e / 48, o = e % 48;
            const float* W = (o<16) ? wg : ((o<32) ? wb : wa);
            Ws[kk*48 + o] = W[(size_t)(k0+kk)*16 + (o & 15)];
        }
        __syncthreads();
        #pragma unroll 4
        for (int kk=0; kk<128; kk++){
            float xv = Xs[row*XS_STRIDE + kk];
            const float* wrow = &Ws[kk*48 + o0];
            #pragma unroll
            for (int j=0;j<24;j+=4){
                float4 w4 = *(const float4*)&wrow[j];
                acc[j]   += xv*w4.x; acc[j+1] += xv*w4.y;
                acc[j+2] += xv*w4.z; acc[j+3] += xv*w4.w;
            }
        }
        __syncthreads();
    }
    int rg = r0 + row;
    #pragma unroll
    for (int j=0;j<24;j++){
        int o = o0 + j;
        int h = o & 15, kind = o >> 4;
        float s = acc[j];
        if (kind==0)      g_gate[rg*16+h] = 1.f/(1.f+__expf(-s));
        else if (kind==1) g_beta[rg*16+h] = 1.f/(1.f+__expf(-s));
        else {
            float v = s + dtb[h];
            float sp = fmaxf(v,0.f) + log1pf(__expf(-fabsf(v)));
            g_dec[rg*16+h] = -__expf(alog[h])*sp;
        }
    }
}

// ================= bf16 mma GEMM, cp.async 3-stage =================
#define GS_A_STRIDE 20
#define GS_B_STRIDE 68
#define GS_A_TILE  (128*GS_A_STRIDE)
#define GS_B_TILE  (32*GS_B_STRIDE)
#define GS_STAGE   (GS_A_TILE + GS_B_TILE)
#define G_SMEM     (3*GS_STAGE*4)

__device__ __forceinline__ void ldsm4(unsigned r[4], uint32_t a){
    asm volatile("ldmatrix.sync.aligned.m8n8.x4.shared.b16 {%0,%1,%2,%3}, [%4];"
        : "=r"(r[0]),"=r"(r[1]),"=r"(r[2]),"=r"(r[3]) : "r"(a));
}
__device__ __forceinline__ void ldsm4t(unsigned r[4], uint32_t a){
    asm volatile("ldmatrix.sync.aligned.m8n8.x4.trans.shared.b16 {%0,%1,%2,%3}, [%4];"
        : "=r"(r[0]),"=r"(r[1]),"=r"(r[2]),"=r"(r[3]) : "r"(a));
}
__device__ __forceinline__ void mma_bf16(float* c, const unsigned* a, unsigned b0, unsigned b1){
    asm volatile("mma.sync.aligned.m16n8k16.row.col.f32.bf16.bf16.f32 "
      "{%0,%1,%2,%3}, {%4,%5,%6,%7}, {%8,%9}, {%0,%1,%2,%3};"
      : "+f"(c[0]),"+f"(c[1]),"+f"(c[2]),"+f"(c[3])
      : "r"(a[0]),"r"(a[1]),"r"(a[2]),"r"(a[3]),"r"(b0),"r"(b1));
}

// mode 0: Cb (bf16) = A@Bw ; mode 1: Cf (fp32) = R + A@Bw
__global__ __launch_bounds__(256) void hgemm(
    const __nv_bfloat16* __restrict__ A, const __nv_bfloat16* __restrict__ Bw,
    const float* __restrict__ R, float* __restrict__ Cf,
    __nv_bfloat16* __restrict__ Cb, int mode)
{
    extern __shared__ float gsm[];
    uint32_t sbase = smem_u32(gsm);

    int t = threadIdx.x, lane = t & 31, warp = t >> 5;
    int wm = warp >> 1, wn = warp & 1;
    int bm = blockIdx.y, bn = blockIdx.x;
    const __nv_bfloat16* Ab = A + (size_t)(bm*128)*1024;
    const __nv_bfloat16* Bb = Bw + (size_t)bn*128;

    float acc[2][8][4];
    #pragma unroll
    for (int mt=0;mt<2;mt++)
        #pragma unroll
        for (int j=0;j<8;j++)
            #pragma unroll
            for (int r=0;r<4;r++) acc[mt][j][r]=0.f;

    auto issue = [&](int it){
        uint32_t st = sbase + (uint32_t)(it % 3)*(GS_STAGE*4);
        #pragma unroll
        for (int u=0;u<2;u++){
            int row = u*64 + (t>>2), ch = t&3;
            uint32_t so = st + (uint32_t)((row*GS_A_STRIDE + ch*4)*4);
            cpa16(so, Ab + (size_t)row*1024 + it*32 + ch*8);
        }
        uint32_t sb = st + GS_A_TILE*4;
        #pragma unroll
        for (int u=0;u<2;u++){
            int row = u*16 + (t>>4), ch = t&15;
            uint32_t so = sb + (uint32_t)((row*GS_B_STRIDE + ch*4)*4);
            cpa16(so, Bb + (size_t)(it*32 + row)*1024 + ch*8);
        }
    };

    issue(0); asm volatile("cp.async.commit_group;" ::: "memory");
    issue(1); asm volatile("cp.async.commit_group;" ::: "memory");

    for (int it=0; it<32; it++){
        if (it < 31) asm volatile("cp.async.wait_group 1;" ::: "memory");
        else         asm volatile("cp.async.wait_group 0;" ::: "memory");
        __syncthreads();
        if (it+2 < 32){
            issue(it+2);
            asm volatile("cp.async.commit_group;" ::: "memory");
        }
        uint32_t sa = sbase + (uint32_t)(it % 3)*(GS_STAGE*4);
        uint32_t sb = sa + GS_A_TILE*4;
        #pragma unroll
        for (int s=0;s<2;s++){
            unsigned af[2][4], bfr[4][4];
            #pragma unroll
            for (int mt=0;mt<2;mt++){
                uint32_t ad = sa + (uint32_t)((((wm*32 + mt*16 + (lane&15))*GS_A_STRIDE)
                                  + s*8 + ((lane>>4)&1)*4)*4);
                ldsm4(af[mt], ad);
            }
            #pragma unroll
            for (int nt=0;nt<4;nt++){
                uint32_t bd = sb + (uint32_t)((((s*16 + (lane&7) + ((lane>>3)&1)*8)*GS_B_STRIDE)
                                  + wn*32 + nt*8 + ((lane>>4)&1)*4)*4);
                ldsm4t(bfr[nt], bd);
            }
            #pragma unroll
            for (int mt=0;mt<2;mt++)
                #pragma unroll
                for (int j=0;j<8;j++)
                    mma_bf16(acc[mt][j], af[mt], bfr[j>>1][(j&1)*2], bfr[j>>1][(j&1)*2+1]);
        }
    }

    int g = lane >> 2, tg = lane & 3;
    #pragma unroll
    for (int mt=0; mt<2; mt++){
        int r0 = bm*128 + wm*32 + mt*16 + g;
        #pragma unroll
        for (int j=0; j<8; j++){
            int col = bn*128 + wn*64 + j*8 + tg*2;
            size_t o0 = (size_t)r0*1024 + col;
            size_t o1 = o0 + (size_t)8*1024;
            if (mode){
                float2 q0 = *(const float2*)&R[o0];
                float2 q1 = *(const float2*)&R[o1];
                *(float2*)&Cf[o0] = make_float2(acc[mt][j][0]+q0.x, acc[mt][j][1]+q0.y);
                *(float2*)&Cf[o1] = make_float2(acc[mt][j][2]+q1.x, acc[mt][j][3]+q1.y);
            } else {
                __nv_bfloat162 v0 = __floats2bfloat162_rn(acc[mt][j][0], acc[mt][j][1]);
                __nv_bfloat162 v1 = __floats2bfloat162_rn(acc[mt][j][2], acc[mt][j][3]);
                *(__nv_bfloat162*)&Cb[o0] = v0;
                *(__nv_bfloat162*)&Cb[o1] = v1;
            }
        }
    }
}

// ================= per-chunk prep (bf16 inputs, ratio-table decay) =================
#define WKS 68
#define PREP_SMEM ((65*WKS + 4096 + 4096 + 64*5 + 8)*4)

__global__ __launch_bounds__(256) void prep_kernel()
{
    extern __shared__ float sm[];
    float* WK    = sm;
    float* Gm    = WK + 65*WKS;
    float* Mb    = Gm + 4096;
    float* cum   = Mb + 4096;
    float* dexpv = cum + 64;
    float* betav = dexpv + 64;
    float* exv   = betav + 64;
    float* rexv  = exv + 64;

    int cid = blockIdx.x;
    int b = cid / (H_*N_);
    int h = (cid / N_) % H_;
    int n = cid % N_;
    int t = threadIdx.x;
    size_t xbase = ((size_t)b*T_ + (size_t)n*C_)*D_ + (size_t)h*64;
    size_t base  = (size_t)cid*4096;

    for (int f = t; f < 65*16; f += 256){
        int r = f >> 4, j4 = (f & 15)*4;
        float4 v;
        if (r == 0 && n == 0) v = make_float4(0.f,0.f,0.f,0.f);
        else v = ld4bf(&g_xb[xbase + ((size_t)r-1)*D_ + j4]);
        *(float4*)&WK[r*WKS + j4] = v;
    }
    if (t < 64){
        int tok = (b*T_ + n*C_ + t)*H_ + h;
        betav[t] = g_beta[tok];
        cum[t]   = g_dec[tok];
    }
    __syncthreads();

    if (t < 65){
        float s = 0.f;
        #pragma unroll
        for (int q=0;q<16;q++){
            float4 v = *(float4*)&WK[t*WKS + q*4];
            s += v.x*v.x + v.y*v.y + v.z*v.z + v.w*v.w;
        }
        float inv = 1.f/fmaxf(sqrtf(s), 1e-12f);
        #pragma unroll
        for (int q=0;q<16;q++){
            float4 v = *(float4*)&WK[t*WKS + q*4];
            v.x*=inv; v.y*=inv; v.z*=inv; v.w*=inv;
            *(float4*)&WK[t*WKS + q*4] = v;
        }
    }
    if (t == 65){
        float s = 0.f;
        for (int c=0;c<64;c++){ s += cum[c]; cum[c] = s; }
    }
    __syncthreads();
    if (t < 64){
        float mid = cum[31];
        dexpv[t] = __expf(cum[t]);
        exv[t]   = __expf(cum[t] - mid);
        rexv[t]  = __expf(mid - cum[t]);
    }

    for (int f = t; f < 1024; f += 256){
        int i = f >> 4, j4 = (f & 15)*4;
        float4 v = ld4bf(&g_vb[xbase + (size_t)i*D_ + j4]);
        float bt = betav[i];
        v.x*=bt; v.y*=bt; v.z*=bt; v.w*=bt;
        *(float4*)&Gm[i*64 + j4] = v;
    }
    __syncthreads();

    float y[64];
    if (t < 128){
        if (t < 64){
            #pragma unroll
            for (int i=0;i<64;i++) y[i] = Gm[i*64 + t];
        } else {
            int jj = t - 64;
            #pragma unroll
            for (int i=0;i<64;i++) y[i] = WK[i*WKS + jj]*betav[i]*dexpv[i];
        }
    }
    __syncthreads();

    {
        int tr = (t >> 4)*4, tc = (t & 15)*4;
        float d[4][4];
        #pragma unroll
        for (int a=0;a<4;a++)
            #pragma unroll
            for (int c=0;c<4;c++) d[a][c]=0.f;
        for (int m4=0; m4<64; m4+=4){
            float4 av[4], cv[4];
            #pragma unroll
            for (int a=0;a<4;a++) av[a] = *(float4*)&WK[(tr+a+1)*WKS + m4];
            #pragma unroll
            for (int c=0;c<4;c++) cv[c] = *(float4*)&WK[(tc+c)*WKS + m4];
            #pragma unroll
            for (int a=0;a<4;a++)
                #pragma unroll
                for (int c=0;c<4;c++)
                    d[a][c] += av[a].x*cv[c].x + av[a].y*cv[c].y
                             + av[a].z*cv[c].z + av[a].w*cv[c].w;
        }
        __syncthreads();
        #pragma unroll
        for (int a=0;a<4;a++)
            #pragma unroll
            for (int c=0;c<4;c++)
                Gm[(tr+a)*64 + tc+c] = d[a][c];
    }
    __syncthreads();

    for (int f = t; f < 4096; f += 256){
        int i = f >> 6, j = f & 63;
        Mb[f] = (j < i) ? (-betav[i]*exv[i]*rexv[j]*Gm[(i-1)*64 + j]) : 0.f;
    }
    __syncthreads();

    if (t < 128){
        #pragma unroll
        for (int kb=0; kb<64; kb+=4){
            y[kb+1] = fmaf(Mb[(kb+1)*64+kb],   y[kb],   y[kb+1]);
            y[kb+2] = fmaf(Mb[(kb+2)*64+kb],   y[kb],   y[kb+2]);
            y[kb+2] = fmaf(Mb[(kb+2)*64+kb+1], y[kb+1], y[kb+2]);
            y[kb+3] = fmaf(Mb[(kb+3)*64+kb],   y[kb],   y[kb+3]);
            y[kb+3] = fmaf(Mb[(kb+3)*64+kb+1], y[kb+1], y[kb+3]);
            y[kb+3] = fmaf(Mb[(kb+3)*64+kb+2], y[kb+2], y[kb+3]);
            #pragma unroll
            for (int i=kb+4; i<64; i++){
                float4 m = *(float4*)&Mb[i*64 + kb];
                y[i] = fmaf(m.x, y[kb],
                       fmaf(m.y, y[kb+1],
                       fmaf(m.z, y[kb+2],
                       fmaf(m.w, y[kb+3], y[i]))));
            }
        }
        if (t < 64){
            #pragma unroll
            for (int i=0;i<64;i++) g_vc[base + i*64 + t] = __float2bfloat16(y[i]);
        } else {
            int jj = t - 64;
            #pragma unroll
            for (int i=0;i<64;i++) g_wkcd[base + i*64 + jj] = __float2bfloat16(-y[i]);
        }
    } else {
        int tt = t - 128;
        for (int f = tt; f < 4096; f += 128){
            int i = f >> 6, j = f & 63;
            g_intra[base + f] = __float2bfloat16(
                (i >= j) ? (exv[i]*rexv[j]*Gm[f]) : 0.f);
        }
        for (int f = tt; f < 1024; f += 128){
            int i = f >> 4, j4 = (f & 15)*4;
            float4 v = *(float4*)&WK[(i+1)*WKS + j4];
            float dv = dexpv[i];
            __nv_bfloat162 lo = __floats2bfloat162_rn(v.x*dv, v.y*dv);
            __nv_bfloat162 hi = __floats2bfloat162_rn(v.z*dv, v.w*dv);
            uint2 pkd = make_uint2(*(unsigned*)&lo, *(unsigned*)&hi);
            *(uint2*)&g_rkd[base + i*64 + j4] = pkd;
        }
        float ex63 = exv[63];
        for (int f = tt; f < 4096; f += 128){
            int jt = f >> 6, ct = f & 63;
            g_wkdw[base + f] = __float2bfloat16(
                WK[ct*WKS + jt]*(ex63*rexv[ct]));
        }
        if (t == 128) g_elast[cid] = __expf(cum[63]);
    }
}

// ================= scan: R16 structure (deferred norm clip) =================
#define SS 36
#define OFF_S     0
#define OFF_VN    9216
#define OFF_VC    18432
#define OFF_W     28672
#define OFF_GATE  102400
#define OFF_MISC  102912
#define SCAN_SMEM 103040
#define W_BUF     36864
#define W_TILE    9216

__global__ __launch_bounds__(256) __cluster_dims__(2,1,1) void scan_kernel()
{
    extern __shared__ float sm[];
    char* smc = (char*)sm;
    float* S     = (float*)(smc + OFF_S);
    float* VN    = (float*)(smc + OFF_VN);
    float* gatev = (float*)(smc + OFF_GATE);
    float* misc  = (float*)(smc + OFF_MISC);

    int bid = blockIdx.x;
    int bh = bid >> 1, half = bid & 1;
    int b = bh >> 4, h = bh & 15;
    int t = threadIdx.x;
    int lane = t & 31, w = t >> 5;
    int ebl = (t & 7) * 4;
    int cbl = (t >> 3) * 2;

    uint32_t sb_u32 = smem_u32(sm);
    uint32_t exch_addr = smem_u32(&misc[12]);
    uint32_t peer = half ^ 1;

    for (int i=t; i<2304; i+=256) S[i]=0.f;
    __syncthreads();

    auto prefetch = [&](int n){
        int p = n & 1;
        size_t gb = ((size_t)bh*64 + n)*4096;
        uint32_t wb = sb_u32 + OFF_W + (uint32_t)p*W_BUF;
        #pragma unroll
        for (int u=0; u<2; u++){
            int q = u*256 + t;
            int row = q >> 3, ch = q & 7;
            uint32_t doff = (uint32_t)(row*144 + ch*16);
            size_t goff = gb + row*64 + ch*8;
            cpa16(wb + 0*W_TILE + doff, g_wkcd  + goff);
            cpa16(wb + 1*W_TILE + doff, g_rkd   + goff);
            cpa16(wb + 2*W_TILE + doff, g_intra + goff);
            cpa16(wb + 3*W_TILE + doff, g_wkdw  + goff);
        }
        {
            int row = t >> 2, ch = t & 3;
            cpa16(sb_u32 + OFF_VC + (uint32_t)(p*5120 + row*80 + ch*16),
                  g_vc + gb + row*64 + half*32 + ch*8);
        }
        if (t < 64)
            cpa4(sb_u32 + OFF_GATE + (uint32_t)(p*256 + t*4),
                 g_gate + ((size_t)b*T_ + n*64 + t)*H_ + h);
        if (t == 0)
            cpa4(sb_u32 + OFF_MISC + (uint32_t)((8+p)*4), g_elast + bh*64 + n);
    };

    prefetch(0); asm volatile("cp.async.commit_group;" ::: "memory");

    float fprev = 1.f;

    for (int n=0; n<64; n++){
        int p = n & 1;
        if (n+1 < 64){
            prefetch(n+1);
            asm volatile("cp.async.commit_group;" ::: "memory");
            asm volatile("cp.async.wait_group 1;" ::: "memory");
        } else {
            asm volatile("cp.async.wait_group 0;" ::: "memory");
        }
        __syncthreads();

        const __nv_bfloat16* VC    = (const __nv_bfloat16*)(smc + OFF_VC + p*5120);
        const __nv_bfloat16* WKCD  = (const __nv_bfloat16*)(smc + OFF_W + p*W_BUF);
        const __nv_bfloat16* RKD   = (const __nv_bfloat16*)(smc + OFF_W + p*W_BUF + W_TILE);
        const __nv_bfloat16* INTRA = (const __nv_bfloat16*)(smc + OFF_W + p*W_BUF + 2*W_TILE);
        const __nv_bfloat16* WKDW  = (const __nv_bfloat16*)(smc + OFF_W + p*W_BUF + 3*W_TILE);

        // phase 1: v_new = vc + fprev*((-wkcd) @ S')
        {
            u64 acc[2][2] = {{0ull,0ull},{0ull,0ull}};
            #pragma unroll 4
            for (int k4=0;k4<64;k4+=4){
                u64x2 s0 = *(u64x2*)&S[(k4+0)*SS + ebl];
                u64x2 s1 = *(u64x2*)&S[(k4+1)*SS + ebl];
                u64x2 s2 = *(u64x2*)&S[(k4+2)*SS + ebl];
                u64x2 s3 = *(u64x2*)&S[(k4+3)*SS + ebl];
                #pragma unroll
                for (int ci=0;ci<2;ci++){
                    float4 wv = ld4bf(&WKCD[(cbl+ci)*72 + k4]);
                    u64 ww;
                    ww = pk2(wv.x); fma2(acc[ci][0], ww, s0.a); fma2(acc[ci][1], ww, s0.b);
                    ww = pk2(wv.y); fma2(acc[ci][0], ww, s1.a); fma2(acc[ci][1], ww, s1.b);
                    ww = pk2(wv.z); fma2(acc[ci][0], ww, s2.a); fma2(acc[ci][1], ww, s2.b);
                    ww = pk2(wv.w); fma2(acc[ci][0], ww, s3.a); fma2(acc[ci][1], ww, s3.b);
                }
            }
            #pragma unroll
            for (int ci=0;ci<2;ci++){
                float4 vcv = ld4bf(&VC[(cbl+ci)*40 + ebl]);
                float2 m0 = up2(acc[ci][0]), m1 = up2(acc[ci][1]);
                u64x2 o;
                o.a = pkf2(fmaf(fprev, m0.x, vcv.x), fmaf(fprev, m0.y, vcv.y));
                o.b = pkf2(fmaf(fprev, m1.x, vcv.z), fmaf(fprev, m1.y, vcv.w));
                *(u64x2*)&VN[(cbl+ci)*SS + ebl] = o;
            }
        }
        __syncthreads();

        // phase 2: o = fprev*(rkd@S') + intra@VN ; ud = wkdw@VN
        u64 oa[2][2] = {{0ull,0ull},{0ull,0ull}};
        u64 ud[2][2] = {{0ull,0ull},{0ull,0ull}};
        {
            #pragma unroll 4
            for (int k4=0;k4<64;k4+=4){
                u64x2 s0 = *(u64x2*)&S[(k4+0)*SS + ebl];
                u64x2 s1 = *(u64x2*)&S[(k4+1)*SS + ebl];
                u64x2 s2 = *(u64x2*)&S[(k4+2)*SS + ebl];
                u64x2 s3 = *(u64x2*)&S[(k4+3)*SS + ebl];
                #pragma unroll
                for (int ci=0;ci<2;ci++){
                    float4 wv = ld4bf(&RKD[(cbl+ci)*72 + k4]);
                    u64 ww;
                    ww = pk2(wv.x); fma2(oa[ci][0], ww, s0.a); fma2(oa[ci][1], ww, s0.b);
                    ww = pk2(wv.y); fma2(oa[ci][0], ww, s1.a); fma2(oa[ci][1], ww, s1.b);
                    ww = pk2(wv.z); fma2(oa[ci][0], ww, s2.a); fma2(oa[ci][1], ww, s2.b);
                    ww = pk2(wv.w); fma2(oa[ci][0], ww, s3.a); fma2(oa[ci][1], ww, s3.b);
                }
            }
            #pragma unroll
            for (int ci=0;ci<2;ci++){
                float2 a0 = up2(oa[ci][0]), a1 = up2(oa[ci][1]);
                oa[ci][0] = pkf2(a0.x*fprev, a0.y*fprev);
                oa[ci][1] = pkf2(a1.x*fprev, a1.y*fprev);
            }
            #pragma unroll 4
            for (int k4=0;k4<64;k4+=4){
                u64x2 v0 = *(u64x2*)&VN[(k4+0)*SS + ebl];
                u64x2 v1 = *(u64x2*)&VN[(k4+1)*SS + ebl];
                u64x2 v2 = *(u64x2*)&VN[(k4+2)*SS + ebl];
                u64x2 v3 = *(u64x2*)&VN[(k4+3)*SS + ebl];
                #pragma unroll
                for (int ci=0;ci<2;ci++){
                    float4 wv = ld4bf(&INTRA[(cbl+ci)*72 + k4]);
                    u64 ww;
                    ww = pk2(wv.x); fma2(oa[ci][0], ww, v0.a); fma2(oa[ci][1], ww, v0.b);
                    ww = pk2(wv.y); fma2(oa[ci][0], ww, v1.a); fma2(oa[ci][1], ww, v1.b);
                    ww = pk2(wv.z); fma2(oa[ci][0], ww, v2.a); fma2(oa[ci][1], ww, v2.b);
                    ww = pk2(wv.w); fma2(oa[ci][0], ww, v3.a); fma2(oa[ci][1], ww, v3.b);
                }
                #pragma unroll
                for (int di=0;di<2;di++){
                    float4 wd = ld4bf(&WKDW[(cbl+di)*72 + k4]);
                    u64 ww;
                    ww = pk2(wd.x); fma2(ud[di][0], ww, v0.a); fma2(ud[di][1], ww, v0.b);
                    ww = pk2(wd.y); fma2(ud[di][0], ww, v1.a); fma2(ud[di][1], ww, v1.b);
                    ww = pk2(wd.z); fma2(ud[di][0], ww, v2.a); fma2(ud[di][1], ww, v2.b);
                    ww = pk2(wd.w); fma2(ud[di][0], ww, v3.a); fma2(ud[di][1], ww, v3.b);
                }
            }
            #pragma unroll
            for (int ci=0;ci<2;ci++){
                float gt = gatev[p*64 + cbl+ci];
                float2 p0 = up2(oa[ci][0]), p1 = up2(oa[ci][1]);
                __nv_bfloat162 b0 = __floats2bfloat162_rn(p0.x*gt, p0.y*gt);
                __nv_bfloat162 b1 = __floats2bfloat162_rn(p1.x*gt, p1.y*gt);
                size_t orow = ((size_t)b*T_ + n*64 + cbl+ci)*D_ + (size_t)h*64 + half*32 + ebl;
                *(__nv_bfloat162*)&g_ogb[orow]   = b0;
                *(__nv_bfloat162*)&g_ogb[orow+2] = b1;
            }
        }
        __syncthreads();

        float el = misc[8 + p] * fprev;
        float partial = 0.f;
        #pragma unroll
        for (int di=0;di<2;di++){
            float2 u0 = up2(ud[di][0]), u1 = up2(ud[di][1]);
            float uu[4] = {u0.x, u0.y, u1.x, u1.y};
            #pragma unroll
            for (int ei=0;ei<4;ei++){
                int idx = (cbl+di)*SS + ebl + ei;
                float sv = fmaf(S[idx], el, uu[ei]);
                S[idx] = sv;
                partial = fmaf(sv, sv, partial);
            }
        }
        #pragma unroll
        for (int off=16; off>0; off>>=1) partial += __shfl_down_sync(0xffffffffu, partial, off);
        if (lane==0) misc[w] = partial;
        __syncthreads();
        if (t==0){
            float s=0.f;
            #pragma unroll
            for (int i=0;i<8;i++) s += misc[i];
            misc[10] = s;
            uint32_t remote;
            asm volatile("mapa.shared::cluster.u32 %0, %1, %2;" : "=r"(remote)
                         : "r"(exch_addr + (n&1)*4), "r"(peer));
            asm volatile("st.shared::cluster.f32 [%0], %1;" :: "r"(remote), "f"(s) : "memory");
        }
        asm volatile("barrier.cluster.arrive.aligned;" ::: "memory");
        asm volatile("barrier.cluster.wait.aligned;" ::: "memory");
        float total = misc[10] + misc[12 + (n&1)];
        float nrm = sqrtf(total);
        fprev = fminf(nrm,100.f)/fmaxf(nrm,1e-6f);
    }
}

extern "C" void kernel_launch(void* const* d_in, const int* in_sizes, int n_in,
                              void* d_out, int out_size) {
    const float* x      = (const float*)d_in[0];
    const float* w_wr   = (const float*)d_in[1];
    const float* w_gate = (const float*)d_in[2];
    const float* w_out  = (const float*)d_in[3];
    const float* w_beta = (const float*)d_in[4];
    const float* w_alph = (const float*)d_in[5];
    const float* dtb    = (const float*)d_in[6];
    const float* alog   = (const float*)d_in[7];
    float* out = (float*)d_out;

    cudaFuncSetAttribute(proj_kernel, cudaFuncAttributeMaxDynamicSharedMemorySize, PROJ_SMEM);
    cudaFuncSetAttribute(prep_kernel, cudaFuncAttributeMaxDynamicSharedMemorySize, PREP_SMEM);
    cudaFuncSetAttribute(scan_kernel, cudaFuncAttributeMaxDynamicSharedMemorySize, SCAN_SMEM);
    cudaFuncSetAttribute(hgemm,       cudaFuncAttributeMaxDynamicSharedMemorySize, G_SMEM);

    __nv_bfloat16 *xb, *ogb, *wb0, *wb1, *vb;
    cudaGetSymbolAddress((void**)&xb,  g_xb);
    cudaGetSymbolAddress((void**)&ogb, g_ogb);
    cudaGetSymbolAddress((void**)&wb0, g_wb0);
    cudaGetSymbolAddress((void**)&wb1, g_wb1);
    cudaGetSymbolAddress((void**)&vb,  g_vb);

    proj_kernel<<<128, 256, PROJ_SMEM>>>(x, w_gate, w_beta, w_alph, dtb, alog);
    cvt_kernel<<<(D_*D_/4 + 255)/256, 256>>>(w_wr, wb0, D_*D_/4);
    cvt_kernel<<<(D_*D_/4 + 255)/256, 256>>>(w_out, wb1, D_*D_/4);
    hgemm<<<dim3(8,128), 256, G_SMEM>>>(xb, wb0, nullptr, nullptr, vb, 0);
    prep_kernel<<<BHN_, 256, PREP_SMEM>>>();
    scan_kernel<<<128, 256, SCAN_SMEM>>>();
    hgemm<<<dim3(8,128), 256, G_SMEM>>>(ogb, wb1, x, out, nullptr, 1);
}